// round 16
// baseline (speedup 1.0000x reference)
#include <cuda_runtime.h>
#include <cuda_bf16.h>
#include <math.h>

#define B 512
#define S 64
#define KNB 8
#define D 16
#define NSTEPS 100
#define NUNITS 128

#define BS    (B*S)       // 32768
#define NGATH (BS/4)      // 8192 gather blocks (4 (b,s) each) -- FIRST in grid
#define NDIFF (B)         // 512 diffusion blocks (1 batch each) -- tail

// ---- device scratch (static, allocation-free) ----
__device__ float g_item[BS * D];
__device__ unsigned int g_cnt[B];   // monotonic; head = (old & 15) == 15

__device__ __forceinline__ float fsigmoid(float a) {
    return __fdividef(1.f, 1.f + __expf(-a));
}

// ---------------------------------------------------------------------------
// Single fused kernel, 128-thread blocks, 14 blocks/SM.
// Gather blocks occupy grid [0, NGATH); diffusion fills the tail.
// ---------------------------------------------------------------------------
__global__ __launch_bounds__(128, 14) void fused_kernel(
    const float* __restrict__ ent_emb,
    const float* __restrict__ rel_emb,
    const float* __restrict__ agg_W, const float* __restrict__ agg_b,
    const float* __restrict__ usr_emb,
    const float* __restrict__ W1, const float* __restrict__ b1,
    const float* __restrict__ W2, const float* __restrict__ b2,
    const float* __restrict__ W3, const float* __restrict__ b3,
    const float* __restrict__ W4, const float* __restrict__ b4,
    const float* __restrict__ se1, const float* __restrict__ se2,
    const float* __restrict__ se3,
    const float* __restrict__ noise_e,
    const float* __restrict__ fc1_W, const float* __restrict__ fc1_b,
    const float* __restrict__ fc2_W, const float* __restrict__ fc2_b,
    const int* __restrict__ u, const int* __restrict__ v,
    const int* __restrict__ t,
    const int* __restrict__ click_seq,
    const int* __restrict__ adj_ent, const int* __restrict__ adj_rel,
    float* __restrict__ out)
{
    int tid = threadIdx.x;

    // ======================= diffusion path (tail blocks) ==================
    if (blockIdx.x >= NGATH) {
        __shared__ float red[128];
        __shared__ float xs[16], ha[128], hb[128], p4[8][16];
        int b = blockIdx.x - NGATH;
        int tb = __ldg(t + b);

        float lg = 0.f;
        if (tid < NSTEPS && tid <= tb) {
            float z = -6.f + 12.f * (float)tid / 99.f;
            float beta = fsigmoid(z) * (0.005f - 1e-5f) + 1e-5f;
            lg = log1pf(-beta);
        }
        red[tid] = lg;
        __syncthreads();
#pragma unroll
        for (int st = 64; st > 0; st >>= 1) {
            if (tid < st) red[tid] += red[tid + st];
            __syncthreads();
        }
        float ap  = __expf(red[0]);
        float ab  = sqrtf(ap);
        float omb = sqrtf(1.f - ap);

        if (tid < 16)
            xs[tid] = __ldg(usr_emb + (size_t)__ldg(u + b) * D + tid) * ab
                    + __ldg(noise_e + b * D + tid) * omb;
        __syncthreads();
        {
            float a = __ldg(b1 + tid) + __ldg(se1 + tb * NUNITS + tid);
#pragma unroll
            for (int d = 0; d < 16; d++)
                a = fmaf(xs[d], __ldg(W1 + d * NUNITS + tid), a);
            ha[tid] = fmaxf(a, 0.f);
        }
        __syncthreads();
        {
            float a0 = 0.f, a1 = 0.f;
#pragma unroll
            for (int i = 0; i < 128; i += 2) {
                a0 = fmaf(ha[i+0], __ldg(W2 + (i+0) * NUNITS + tid), a0);
                a1 = fmaf(ha[i+1], __ldg(W2 + (i+1) * NUNITS + tid), a1);
            }
            float a = __ldg(b2 + tid) + __ldg(se2 + tb * NUNITS + tid) + a0 + a1;
            hb[tid] = fmaxf(a, 0.f);
        }
        __syncthreads();
        {
            float a0 = 0.f, a1 = 0.f;
#pragma unroll
            for (int i = 0; i < 128; i += 2) {
                a0 = fmaf(hb[i+0], __ldg(W3 + (i+0) * NUNITS + tid), a0);
                a1 = fmaf(hb[i+1], __ldg(W3 + (i+1) * NUNITS + tid), a1);
            }
            float a = __ldg(b3 + tid) + __ldg(se3 + tb * NUNITS + tid) + a0 + a1;
            ha[tid] = fmaxf(a, 0.f);
        }
        __syncthreads();
        {
            int g = tid >> 4, d = tid & 15;
            float a = 0.f;
#pragma unroll
            for (int i = 0; i < 16; i++)
                a = fmaf(ha[g * 16 + i], __ldg(W4 + (g * 16 + i) * D + d), a);
            p4[g][d] = a;
        }
        __syncthreads();
        if (tid < 16) {
            float a = __ldg(b4 + tid);
#pragma unroll
            for (int g = 0; g < 8; g++) a += p4[g][tid];
            out[b * (1 + D) + 1 + tid] = a;
        }
        return;
    }

    // ======================= gather path (R13 structure) ====================
    __shared__ float urel_s[64];
    __shared__ float Wm[256], bbias[16];
    __shared__ float tmp1s[4][8][20];
    __shared__ float out1s[4][8][18];
    __shared__ float p0s[4][8];
    __shared__ float t0s[4][20];
    __shared__ float tfs[4][17];
    __shared__ int   headflag;

    int gb  = blockIdx.x;
    int bsl = tid >> 5, n = (tid >> 2) & 7, q = tid & 3;
    int bs  = gb * 4 + bsl;
    int bq  = bs >> 6;

    Wm[tid]       = __ldg(agg_W + tid);
    Wm[tid + 128] = __ldg(agg_W + tid + 128);
    if (tid < 16) bbias[tid] = __ldg(agg_b + tid);

    // per-block urel table
    if (tid < 64) {
        const float4* uu = (const float4*)usr_emb + (size_t)__ldg(u + bq) * 4;
        const float4* rv = (const float4*)rel_emb + tid * 4;
        float4 a0 = __ldg(uu), a1 = __ldg(uu + 1), a2 = __ldg(uu + 2), a3 = __ldg(uu + 3);
        float4 c0 = __ldg(rv), c1 = __ldg(rv + 1), c2 = __ldg(rv + 2), c3 = __ldg(rv + 3);
        float sd = a0.x*c0.x + a0.y*c0.y + a0.z*c0.z + a0.w*c0.w
                 + a1.x*c1.x + a1.y*c1.y + a1.z*c1.z + a1.w*c1.w
                 + a2.x*c2.x + a2.y*c2.y + a2.z*c2.z + a2.w*c2.w
                 + a3.x*c3.x + a3.y*c3.y + a3.z*c3.z + a3.w*c3.w;
        urel_s[tid] = sd * (1.0f / 16.0f);
    }

    // -------- index chain (per warp = one bs) --------
    const float4* E = (const float4*)ent_emb;
    int e0 = __ldg(click_seq + bs);
    int e1 = __ldg(adj_ent + (size_t)e0 * KNB + n);
    int r0 = __ldg(adj_rel + (size_t)e0 * KNB + n);
    int2 e2p = __ldg((const int2*)(adj_ent + (size_t)e1 * KNB) + q);
    int2 r1p = __ldg((const int2*)(adj_rel + (size_t)e1 * KNB) + q);

    // single-use embedding rows: streaming (evict-first) loads
    float4 e1v = __ldcs(E + (size_t)e1 * 4 + q);
    float4 ev0v = make_float4(0.f, 0.f, 0.f, 0.f);
    if (n == 0) ev0v = __ldcs(E + (size_t)e0 * 4 + q);

    __syncthreads();   // sync1: urel_s ready

    // -------- p1 softmax (no max-sub: |score| << 1) --------
    float ew0 = __expf(urel_s[r1p.x]);
    float ew1 = __expf(urel_s[r1p.y]);
    float sum = ew0 + ew1;
    sum += __shfl_xor_sync(0xffffffffu, sum, 1);
    sum += __shfl_xor_sync(0xffffffffu, sum, 2);
    float inv = __fdividef(1.f, sum);
    float w0 = ew0 * inv, w1 = ew1 * inv;

    // distribute all 8 (e2, w) across the 4-lane group
    int lb = (tid & 31) & ~3;
    int eA0 = __shfl_sync(0xffffffffu, e2p.x, lb+0), eB0 = __shfl_sync(0xffffffffu, e2p.y, lb+0);
    int eA1 = __shfl_sync(0xffffffffu, e2p.x, lb+1), eB1 = __shfl_sync(0xffffffffu, e2p.y, lb+1);
    int eA2 = __shfl_sync(0xffffffffu, e2p.x, lb+2), eB2 = __shfl_sync(0xffffffffu, e2p.y, lb+2);
    int eA3 = __shfl_sync(0xffffffffu, e2p.x, lb+3), eB3 = __shfl_sync(0xffffffffu, e2p.y, lb+3);
    float wA0 = __shfl_sync(0xffffffffu, w0, lb+0), wB0 = __shfl_sync(0xffffffffu, w1, lb+0);
    float wA1 = __shfl_sync(0xffffffffu, w0, lb+1), wB1 = __shfl_sync(0xffffffffu, w1, lb+1);
    float wA2 = __shfl_sync(0xffffffffu, w0, lb+2), wB2 = __shfl_sync(0xffffffffu, w1, lb+2);
    float wA3 = __shfl_sync(0xffffffffu, w0, lb+3), wB3 = __shfl_sync(0xffffffffu, w1, lb+3);

    // -------- gather wave 1 (streaming) --------
    float4 v0 = __ldcs(E + (size_t)eA0 * 4 + q);
    float4 v1 = __ldcs(E + (size_t)eB0 * 4 + q);
    float4 v2 = __ldcs(E + (size_t)eA1 * 4 + q);
    float4 v3 = __ldcs(E + (size_t)eB1 * 4 + q);

    // -------- p0 softmax + t0 reduction (ALU under wave-1 latency) --------
    float p0e = __expf(urel_s[r0]);
    float p0su = p0e;
    p0su += __shfl_xor_sync(0xffffffffu, p0su, 4);
    p0su += __shfl_xor_sync(0xffffffffu, p0su, 8);
    p0su += __shfl_xor_sync(0xffffffffu, p0su, 16);
    float p0w = __fdividef(p0e, p0su);
    if (q == 0) p0s[bsl][n] = p0w;

    float tx = p0w * e1v.x, ty = p0w * e1v.y, tz = p0w * e1v.z, tw = p0w * e1v.w;
#pragma unroll
    for (int msk = 4; msk <= 16; msk <<= 1) {
        tx += __shfl_xor_sync(0xffffffffu, tx, msk);
        ty += __shfl_xor_sync(0xffffffffu, ty, msk);
        tz += __shfl_xor_sync(0xffffffffu, tz, msk);
        tw += __shfl_xor_sync(0xffffffffu, tw, msk);
    }
    if (n == 0) {
        int qq = q * 4;
        t0s[bsl][qq+0] = ev0v.x + tx;
        t0s[bsl][qq+1] = ev0v.y + ty;
        t0s[bsl][qq+2] = ev0v.z + tz;
        t0s[bsl][qq+3] = ev0v.w + tw;
    }

    // -------- consume wave 1 --------
    float accx = wA0*v0.x + wB0*v1.x + wA1*v2.x + wB1*v3.x;
    float accy = wA0*v0.y + wB0*v1.y + wA1*v2.y + wB1*v3.y;
    float accz = wA0*v0.z + wB0*v1.z + wA1*v2.z + wB1*v3.z;
    float accw = wA0*v0.w + wB0*v1.w + wA1*v2.w + wB1*v3.w;

    // -------- gather wave 2 (streaming) --------
    float4 v4 = __ldcs(E + (size_t)eA2 * 4 + q);
    float4 v5 = __ldcs(E + (size_t)eB2 * 4 + q);
    float4 v6 = __ldcs(E + (size_t)eA3 * 4 + q);
    float4 v7 = __ldcs(E + (size_t)eB3 * 4 + q);

    accx += wA2*v4.x + wB2*v5.x + wA3*v6.x + wB3*v7.x;
    accy += wA2*v4.y + wB2*v5.y + wA3*v6.y + wB3*v7.y;
    accz += wA2*v4.z + wB2*v5.z + wA3*v6.z + wB3*v7.z;
    accw += wA2*v4.w + wB2*v5.w + wA3*v6.w + wB3*v7.w;

    {
        int qq = q * 4;
        tmp1s[bsl][n][qq+0] = e1v.x + accx;
        tmp1s[bsl][n][qq+1] = e1v.y + accy;
        tmp1s[bsl][n][qq+2] = e1v.z + accz;
        tmp1s[bsl][n][qq+3] = e1v.w + accw;
    }
    __syncthreads();   // sync2: tmp1s, t0s, p0s ready

    // -------- register-resident weight column --------
    int dp = tid & 15;
    float Wcol[16];
#pragma unroll
    for (int d = 0; d < 16; d++) Wcol[d] = Wm[d * 16 + dp];
    float bcol = bbias[dp];

    // -------- hop1 linear + sigmoid: 4 bl per thread --------
    {
        int n2 = tid >> 4;
#pragma unroll
        for (int bl = 0; bl < 4; bl++) {
            float a = bcol;
#pragma unroll
            for (int d = 0; d < 16; d++)
                a = fmaf(tmp1s[bl][n2][d], Wcol[d], a);
            out1s[bl][n2][dp] = fsigmoid(a);
        }
    }
    // -------- o0 (independent; same phase) --------
    float o0 = 0.f;
    int bl4 = tid >> 4;
    if (tid < 64) {
        float a = bcol;
#pragma unroll
        for (int d2 = 0; d2 < 16; d2++)
            a = fmaf(t0s[bl4][d2], Wcol[d2], a);
        o0 = fsigmoid(a);
    }
    __syncthreads();   // sync3: out1s ready

    if (tid < 64) {
        float tf = o0;
#pragma unroll
        for (int k = 0; k < 8; k++)
            tf = fmaf(p0s[bl4][k], out1s[bl4][k][dp], tf);
        tfs[bl4][dp] = tf;
        __syncwarp(0xffffffffu);
        float a = bcol;
#pragma unroll
        for (int d2 = 0; d2 < 16; d2++)
            a = fmaf(tfs[bl4][d2], Wcol[d2], a);
        g_item[(size_t)(gb * 4 + bl4) * 16 + dp] = fmaxf(tanhf(a), 0.f);
    }

    // -------- last-block-per-batch fusion head (mod-16 counter) --------
    __threadfence();
    __syncthreads();
    if (tid == 0) {
        unsigned int old = atomicAdd(&g_cnt[bq], 1u);
        headflag = ((old & 15u) == 15u);
    }
    __syncthreads();
    if (!headflag) return;

    __shared__ float ps[8][16], pm[8][16], fus[32], hh[64];
    {
        int d = tid & 15, sc = tid >> 4;
        float s = 0.f, mmx = -1e30f;
#pragma unroll
        for (int j = 0; j < 8; j++) {
            float vv = __ldcg(g_item + ((size_t)bq * S + sc * 8 + j) * D + d);
            s += vv;
            mmx = fmaxf(mmx, vv);
        }
        ps[sc][d] = s;
        pm[sc][d] = mmx;
    }
    __syncthreads();
    if (tid < 16) {
        float s = 0.f, mmx = -1e30f;
#pragma unroll
        for (int c = 0; c < 8; c++) { s += ps[c][tid]; mmx = fmaxf(mmx, pm[c][tid]); }
        fus[tid]      = fmaxf(s, 0.f);
        fus[16 + tid] = fmaxf(mmx, 0.f);
    }
    __syncthreads();
    if (tid < 64) {
        float a = __ldg(fc1_b + tid);
#pragma unroll
        for (int i = 0; i < 32; i++)
            a = fmaf(fus[i], __ldg(fc1_W + i * 64 + tid), a);
        hh[tid] = fmaxf(a, 0.f);
    }
    __syncthreads();
    if (tid < 16) {
        float a = __ldg(fc2_b + tid);
#pragma unroll
        for (int i = 0; i < 64; i++)
            a = fmaf(hh[i], __ldg(fc2_W + i * D + tid), a);
        float f = fmaxf(a, 0.f);
        float p = f * __ldg(ent_emb + (size_t)__ldg(v + bq) * D + tid);
        p += __shfl_xor_sync(0xffffu, p, 8);
        p += __shfl_xor_sync(0xffffu, p, 4);
        p += __shfl_xor_sync(0xffffu, p, 2);
        p += __shfl_xor_sync(0xffffu, p, 1);
        if (tid == 0)
            out[bq * (1 + D)] = fsigmoid(p);
    }
}

// ---------------------------------------------------------------------------
extern "C" void kernel_launch(void* const* d_in, const int* in_sizes, int n_in,
                              void* d_out, int out_size)
{
    const float* usr_emb  = (const float*)d_in[0];
    const float* ent_emb  = (const float*)d_in[1];
    const float* rel_emb  = (const float*)d_in[2];
    const float* agg_W    = (const float*)d_in[3];
    const float* agg_b    = (const float*)d_in[4];
    const float* fc1_W    = (const float*)d_in[5];
    const float* fc1_b    = (const float*)d_in[6];
    const float* fc2_W    = (const float*)d_in[7];
    const float* fc2_b    = (const float*)d_in[8];
    const float* mlp_W1   = (const float*)d_in[9];
    const float* mlp_b1   = (const float*)d_in[10];
    const float* mlp_W2   = (const float*)d_in[11];
    const float* mlp_b2   = (const float*)d_in[12];
    const float* mlp_W3   = (const float*)d_in[13];
    const float* mlp_b3   = (const float*)d_in[14];
    const float* mlp_W4   = (const float*)d_in[15];
    const float* mlp_b4   = (const float*)d_in[16];
    const float* se1      = (const float*)d_in[17];
    const float* se2      = (const float*)d_in[18];
    const float* se3      = (const float*)d_in[19];
    const float* noise_e  = (const float*)d_in[20];
    const int*   u        = (const int*)d_in[21];
    const int*   v        = (const int*)d_in[22];
    const int*   click    = (const int*)d_in[23];
    const int*   adj_ent  = (const int*)d_in[24];
    const int*   adj_rel  = (const int*)d_in[25];
    const int*   t        = (const int*)d_in[26];
    float* out = (float*)d_out;

    fused_kernel<<<NGATH + NDIFF, 128>>>(ent_emb, rel_emb, agg_W, agg_b, usr_emb,
                                         mlp_W1, mlp_b1, mlp_W2, mlp_b2,
                                         mlp_W3, mlp_b3, mlp_W4, mlp_b4,
                                         se1, se2, se3, noise_e,
                                         fc1_W, fc1_b, fc2_W, fc2_b,
                                         u, v, t, click, adj_ent, adj_rel, out);
}

// round 17
// speedup vs baseline: 1.0302x; 1.0302x over previous
#include <cuda_runtime.h>
#include <cuda_bf16.h>
#include <math.h>

#define B 512
#define S 64
#define KNB 8
#define D 16
#define NSTEPS 100
#define NUNITS 128

#define BS    (B*S)       // 32768
#define NDIFF (B/2)       // 256 diffusion blocks (2 batches each), FIRST
#define NGATH (BS/8)      // 4096 gather blocks (8 (b,s) each)

// ---- device scratch (static, allocation-free) ----
__device__ float g_item[BS * D];
__device__ unsigned int g_cnt[B];   // monotonic; head = (old & 7) == 7

__device__ __forceinline__ float fsigmoid(float a) {
    return __fdividef(1.f, 1.f + __expf(-a));
}

// ---------------------------------------------------------------------------
// Single fused kernel, 256-thread blocks, 8 blocks/SM (64 warps = 100% occ).
//   blocks [0, NDIFF)           : diffusion MLP, 2 batches each
//   blocks [NDIFF, NDIFF+NGATH) : KGCN chain for 8 (b,s); 8th-arriving block
//                                 per batch runs the fusion head.
// ---------------------------------------------------------------------------
__global__ __launch_bounds__(256, 8) void fused_kernel(
    const float* __restrict__ ent_emb,
    const float* __restrict__ rel_emb,
    const float* __restrict__ agg_W, const float* __restrict__ agg_b,
    const float* __restrict__ usr_emb,
    const float* __restrict__ W1, const float* __restrict__ b1,
    const float* __restrict__ W2, const float* __restrict__ b2,
    const float* __restrict__ W3, const float* __restrict__ b3,
    const float* __restrict__ W4, const float* __restrict__ b4,
    const float* __restrict__ se1, const float* __restrict__ se2,
    const float* __restrict__ se3,
    const float* __restrict__ noise_e,
    const float* __restrict__ fc1_W, const float* __restrict__ fc1_b,
    const float* __restrict__ fc2_W, const float* __restrict__ fc2_b,
    const int* __restrict__ u, const int* __restrict__ v,
    const int* __restrict__ t,
    const int* __restrict__ click_seq,
    const int* __restrict__ adj_ent, const int* __restrict__ adj_rel,
    float* __restrict__ out)
{
    int tid = threadIdx.x;

    // ======================= diffusion path =======================
    if (blockIdx.x < NDIFF) {
        __shared__ float red[256];
        __shared__ float xs[2][16], ha[2][128], hb[2][128], p4[2][8][16];
        int bb2 = tid >> 7, tt = tid & 127;
        int b = blockIdx.x * 2 + bb2;
        int tb = __ldg(t + b);

        float lg = 0.f;
        if (tt < NSTEPS && tt <= tb) {
            float z = -6.f + 12.f * (float)tt / 99.f;
            float beta = fsigmoid(z) * (0.005f - 1e-5f) + 1e-5f;
            lg = log1pf(-beta);
        }
        red[tid] = lg;
        __syncthreads();
#pragma unroll
        for (int st = 64; st > 0; st >>= 1) {
            if (tt < st) red[bb2 * 128 + tt] += red[bb2 * 128 + tt + st];
            __syncthreads();
        }
        float ap  = __expf(red[bb2 * 128]);
        float ab  = sqrtf(ap);
        float omb = sqrtf(1.f - ap);

        if (tt < 16)
            xs[bb2][tt] = __ldg(usr_emb + (size_t)__ldg(u + b) * D + tt) * ab
                        + __ldg(noise_e + b * D + tt) * omb;
        __syncthreads();
        {
            float a = __ldg(b1 + tt) + __ldg(se1 + tb * NUNITS + tt);
#pragma unroll
            for (int d = 0; d < 16; d++)
                a = fmaf(xs[bb2][d], __ldg(W1 + d * NUNITS + tt), a);
            ha[bb2][tt] = fmaxf(a, 0.f);
        }
        __syncthreads();
        {
            float a0 = 0.f, a1 = 0.f;
#pragma unroll
            for (int i = 0; i < 128; i += 2) {
                a0 = fmaf(ha[bb2][i+0], __ldg(W2 + (i+0) * NUNITS + tt), a0);
                a1 = fmaf(ha[bb2][i+1], __ldg(W2 + (i+1) * NUNITS + tt), a1);
            }
            float a = __ldg(b2 + tt) + __ldg(se2 + tb * NUNITS + tt) + a0 + a1;
            hb[bb2][tt] = fmaxf(a, 0.f);
        }
        __syncthreads();
        {
            float a0 = 0.f, a1 = 0.f;
#pragma unroll
            for (int i = 0; i < 128; i += 2) {
                a0 = fmaf(hb[bb2][i+0], __ldg(W3 + (i+0) * NUNITS + tt), a0);
                a1 = fmaf(hb[bb2][i+1], __ldg(W3 + (i+1) * NUNITS + tt), a1);
            }
            float a = __ldg(b3 + tt) + __ldg(se3 + tb * NUNITS + tt) + a0 + a1;
            ha[bb2][tt] = fmaxf(a, 0.f);
        }
        __syncthreads();
        {
            int g = tt >> 4, d = tt & 15;
            float a = 0.f;
#pragma unroll
            for (int i = 0; i < 16; i++)
                a = fmaf(ha[bb2][g * 16 + i], __ldg(W4 + (g * 16 + i) * D + d), a);
            p4[bb2][g][d] = a;
        }
        __syncthreads();
        if (tt < 16) {
            float a = __ldg(b4 + tt);
#pragma unroll
            for (int g = 0; g < 8; g++) a += p4[bb2][g][tt];
            out[b * (1 + D) + 1 + tt] = a;
        }
        return;
    }

    // ======================= gather path (8 bs per block) ===================
    __shared__ float urel_s[64];
    __shared__ float Wm[256], bbias[16];
    __shared__ float tmp1s[8][8][20];
    __shared__ float out1s[8][8][18];
    __shared__ float p0s[8][8];
    __shared__ float t0s[8][20];
    __shared__ float tfs[8][17];
    __shared__ int   headflag;

    int gb  = blockIdx.x - NDIFF;
    int bsl = tid >> 5, n = (tid >> 2) & 7, q = tid & 3;
    int bs  = gb * 8 + bsl;
    int bq  = bs >> 6;                 // same batch for all 8 warps

    Wm[tid] = __ldg(agg_W + tid);
    if (tid < 16) bbias[tid] = __ldg(agg_b + tid);

    // per-block urel table (serves all 8 bs)
    if (tid < 64) {
        const float4* uu = (const float4*)usr_emb + (size_t)__ldg(u + bq) * 4;
        const float4* rv = (const float4*)rel_emb + tid * 4;
        float4 a0 = __ldg(uu), a1 = __ldg(uu + 1), a2 = __ldg(uu + 2), a3 = __ldg(uu + 3);
        float4 c0 = __ldg(rv), c1 = __ldg(rv + 1), c2 = __ldg(rv + 2), c3 = __ldg(rv + 3);
        float sd = a0.x*c0.x + a0.y*c0.y + a0.z*c0.z + a0.w*c0.w
                 + a1.x*c1.x + a1.y*c1.y + a1.z*c1.z + a1.w*c1.w
                 + a2.x*c2.x + a2.y*c2.y + a2.z*c2.z + a2.w*c2.w
                 + a3.x*c3.x + a3.y*c3.y + a3.z*c3.z + a3.w*c3.w;
        urel_s[tid] = sd * (1.0f / 16.0f);
    }

    // -------- index chain (per warp = one bs) --------
    const float4* E = (const float4*)ent_emb;
    int e0 = __ldg(click_seq + bs);
    int e1 = __ldg(adj_ent + (size_t)e0 * KNB + n);
    int r0 = __ldg(adj_rel + (size_t)e0 * KNB + n);
    int2 e2p = __ldg((const int2*)(adj_ent + (size_t)e1 * KNB) + q);
    int2 r1p = __ldg((const int2*)(adj_rel + (size_t)e1 * KNB) + q);

    float4 e1v = __ldg(E + (size_t)e1 * 4 + q);
    float4 ev0v = make_float4(0.f, 0.f, 0.f, 0.f);
    if (n == 0) ev0v = __ldg(E + (size_t)e0 * 4 + q);

    __syncthreads();   // sync1: urel_s ready

    // -------- p1 softmax (no max-sub: |score| << 1) --------
    float ew0 = __expf(urel_s[r1p.x]);
    float ew1 = __expf(urel_s[r1p.y]);
    float sum = ew0 + ew1;
    sum += __shfl_xor_sync(0xffffffffu, sum, 1);
    sum += __shfl_xor_sync(0xffffffffu, sum, 2);
    float inv = __fdividef(1.f, sum);
    float w0 = ew0 * inv, w1 = ew1 * inv;

    // distribute all 8 (e2, w) across the 4-lane group
    int lb = (tid & 31) & ~3;
    int eA0 = __shfl_sync(0xffffffffu, e2p.x, lb+0), eB0 = __shfl_sync(0xffffffffu, e2p.y, lb+0);
    int eA1 = __shfl_sync(0xffffffffu, e2p.x, lb+1), eB1 = __shfl_sync(0xffffffffu, e2p.y, lb+1);
    int eA2 = __shfl_sync(0xffffffffu, e2p.x, lb+2), eB2 = __shfl_sync(0xffffffffu, e2p.y, lb+2);
    int eA3 = __shfl_sync(0xffffffffu, e2p.x, lb+3), eB3 = __shfl_sync(0xffffffffu, e2p.y, lb+3);
    float wA0 = __shfl_sync(0xffffffffu, w0, lb+0), wB0 = __shfl_sync(0xffffffffu, w1, lb+0);
    float wA1 = __shfl_sync(0xffffffffu, w0, lb+1), wB1 = __shfl_sync(0xffffffffu, w1, lb+1);
    float wA2 = __shfl_sync(0xffffffffu, w0, lb+2), wB2 = __shfl_sync(0xffffffffu, w1, lb+2);
    float wA3 = __shfl_sync(0xffffffffu, w0, lb+3), wB3 = __shfl_sync(0xffffffffu, w1, lb+3);

    // -------- gather wave 1 (streaming) --------
    float4 v0 = __ldcs(E + (size_t)eA0 * 4 + q);
    float4 v1 = __ldcs(E + (size_t)eB0 * 4 + q);
    float4 v2 = __ldcs(E + (size_t)eA1 * 4 + q);
    float4 v3 = __ldcs(E + (size_t)eB1 * 4 + q);

    // -------- p0 softmax + t0 reduction (ALU under wave-1 latency) --------
    float p0e = __expf(urel_s[r0]);
    float p0su = p0e;
    p0su += __shfl_xor_sync(0xffffffffu, p0su, 4);
    p0su += __shfl_xor_sync(0xffffffffu, p0su, 8);
    p0su += __shfl_xor_sync(0xffffffffu, p0su, 16);
    float p0w = __fdividef(p0e, p0su);
    if (q == 0) p0s[bsl][n] = p0w;

    float tx = p0w * e1v.x, ty = p0w * e1v.y, tz = p0w * e1v.z, tw = p0w * e1v.w;
#pragma unroll
    for (int msk = 4; msk <= 16; msk <<= 1) {
        tx += __shfl_xor_sync(0xffffffffu, tx, msk);
        ty += __shfl_xor_sync(0xffffffffu, ty, msk);
        tz += __shfl_xor_sync(0xffffffffu, tz, msk);
        tw += __shfl_xor_sync(0xffffffffu, tw, msk);
    }
    if (n == 0) {
        int qq = q * 4;
        t0s[bsl][qq+0] = ev0v.x + tx;
        t0s[bsl][qq+1] = ev0v.y + ty;
        t0s[bsl][qq+2] = ev0v.z + tz;
        t0s[bsl][qq+3] = ev0v.w + tw;
    }

    // -------- consume wave 1 --------
    float accx = wA0*v0.x + wB0*v1.x + wA1*v2.x + wB1*v3.x;
    float accy = wA0*v0.y + wB0*v1.y + wA1*v2.y + wB1*v3.y;
    float accz = wA0*v0.z + wB0*v1.z + wA1*v2.z + wB1*v3.z;
    float accw = wA0*v0.w + wB0*v1.w + wA1*v2.w + wB1*v3.w;

    // -------- gather wave 2 (streaming) --------
    float4 v4 = __ldcs(E + (size_t)eA2 * 4 + q);
    float4 v5 = __ldcs(E + (size_t)eB2 * 4 + q);
    float4 v6 = __ldcs(E + (size_t)eA3 * 4 + q);
    float4 v7 = __ldcs(E + (size_t)eB3 * 4 + q);

    accx += wA2*v4.x + wB2*v5.x + wA3*v6.x + wB3*v7.x;
    accy += wA2*v4.y + wB2*v5.y + wA3*v6.y + wB3*v7.y;
    accz += wA2*v4.z + wB2*v5.z + wA3*v6.z + wB3*v7.z;
    accw += wA2*v4.w + wB2*v5.w + wA3*v6.w + wB3*v7.w;

    {
        int qq = q * 4;
        tmp1s[bsl][n][qq+0] = e1v.x + accx;
        tmp1s[bsl][n][qq+1] = e1v.y + accy;
        tmp1s[bsl][n][qq+2] = e1v.z + accz;
        tmp1s[bsl][n][qq+3] = e1v.w + accw;
    }
    __syncthreads();   // sync2: tmp1s, t0s, p0s ready

    // -------- register-resident weight column --------
    int dp = tid & 15;
    float Wcol[16];
#pragma unroll
    for (int d = 0; d < 16; d++) Wcol[d] = Wm[d * 16 + dp];
    float bcol = bbias[dp];

    // -------- hop1 linear + sigmoid: 4 bl per thread --------
    {
        int r = tid >> 4;            // 0..15
        int n2 = r & 7;
        int blb = (r >> 3) * 4;      // 0 or 4
#pragma unroll
        for (int j = 0; j < 4; j++) {
            int bl = blb + j;
            float a = bcol;
#pragma unroll
            for (int d = 0; d < 16; d++)
                a = fmaf(tmp1s[bl][n2][d], Wcol[d], a);
            out1s[bl][n2][dp] = fsigmoid(a);
        }
    }
    // -------- o0 (tid<128; independent; same phase) --------
    float o0 = 0.f;
    int bl8 = tid >> 4;              // 0..7 for tid<128
    if (tid < 128) {
        float a = bcol;
#pragma unroll
        for (int d2 = 0; d2 < 16; d2++)
            a = fmaf(t0s[bl8][d2], Wcol[d2], a);
        o0 = fsigmoid(a);
    }
    __syncthreads();   // sync3: out1s ready

    if (tid < 128) {
        float tf = o0;
#pragma unroll
        for (int k = 0; k < 8; k++)
            tf = fmaf(p0s[bl8][k], out1s[bl8][k][dp], tf);
        tfs[bl8][dp] = tf;
        __syncwarp(0xffffffffu);
        float a = bcol;
#pragma unroll
        for (int d2 = 0; d2 < 16; d2++)
            a = fmaf(tfs[bl8][d2], Wcol[d2], a);
        g_item[(size_t)(gb * 8 + bl8) * 16 + dp] = fmaxf(tanhf(a), 0.f);
    }

    // -------- last-block-per-batch fusion head (mod-8 counter) --------
    __threadfence();
    __syncthreads();
    if (tid == 0) {
        unsigned int old = atomicAdd(&g_cnt[bq], 1u);
        headflag = ((old & 7u) == 7u);
    }
    __syncthreads();
    if (!headflag) return;

    __shared__ float ps[16][16], pm[16][16], fus[32], hh[64];
    {
        int d = tid & 15, sc = tid >> 4;   // sc 0..15
        float s = 0.f, mmx = -1e30f;
#pragma unroll
        for (int j = 0; j < 4; j++) {
            float vv = __ldcg(g_item + ((size_t)bq * S + sc * 4 + j) * D + d);
            s += vv;
            mmx = fmaxf(mmx, vv);
        }
        ps[sc][d] = s;
        pm[sc][d] = mmx;
    }
    __syncthreads();
    if (tid < 16) {
        float s = 0.f, mmx = -1e30f;
#pragma unroll
        for (int c = 0; c < 16; c++) { s += ps[c][tid]; mmx = fmaxf(mmx, pm[c][tid]); }
        fus[tid]      = fmaxf(s, 0.f);
        fus[16 + tid] = fmaxf(mmx, 0.f);
    }
    __syncthreads();
    if (tid < 64) {
        float a = __ldg(fc1_b + tid);
#pragma unroll
        for (int i = 0; i < 32; i++)
            a = fmaf(fus[i], __ldg(fc1_W + i * 64 + tid), a);
        hh[tid] = fmaxf(a, 0.f);
    }
    __syncthreads();
    if (tid < 16) {
        float a = __ldg(fc2_b + tid);
#pragma unroll
        for (int i = 0; i < 64; i++)
            a = fmaf(hh[i], __ldg(fc2_W + i * D + tid), a);
        float f = fmaxf(a, 0.f);
        float p = f * __ldg(ent_emb + (size_t)__ldg(v + bq) * D + tid);
        p += __shfl_xor_sync(0xffffu, p, 8);
        p += __shfl_xor_sync(0xffffu, p, 4);
        p += __shfl_xor_sync(0xffffu, p, 2);
        p += __shfl_xor_sync(0xffffu, p, 1);
        if (tid == 0)
            out[bq * (1 + D)] = fsigmoid(p);
    }
}

// ---------------------------------------------------------------------------
extern "C" void kernel_launch(void* const* d_in, const int* in_sizes, int n_in,
                              void* d_out, int out_size)
{
    const float* usr_emb  = (const float*)d_in[0];
    const float* ent_emb  = (const float*)d_in[1];
    const float* rel_emb  = (const float*)d_in[2];
    const float* agg_W    = (const float*)d_in[3];
    const float* agg_b    = (const float*)d_in[4];
    const float* fc1_W    = (const float*)d_in[5];
    const float* fc1_b    = (const float*)d_in[6];
    const float* fc2_W    = (const float*)d_in[7];
    const float* fc2_b    = (const float*)d_in[8];
    const float* mlp_W1   = (const float*)d_in[9];
    const float* mlp_b1   = (const float*)d_in[10];
    const float* mlp_W2   = (const float*)d_in[11];
    const float* mlp_b2   = (const float*)d_in[12];
    const float* mlp_W3   = (const float*)d_in[13];
    const float* mlp_b3   = (const float*)d_in[14];
    const float* mlp_W4   = (const float*)d_in[15];
    const float* mlp_b4   = (const float*)d_in[16];
    const float* se1      = (const float*)d_in[17];
    const float* se2      = (const float*)d_in[18];
    const float* se3      = (const float*)d_in[19];
    const float* noise_e  = (const float*)d_in[20];
    const int*   u        = (const int*)d_in[21];
    const int*   v        = (const int*)d_in[22];
    const int*   click    = (const int*)d_in[23];
    const int*   adj_ent  = (const int*)d_in[24];
    const int*   adj_rel  = (const int*)d_in[25];
    const int*   t        = (const int*)d_in[26];
    float* out = (float*)d_out;

    fused_kernel<<<NDIFF + NGATH, 256>>>(ent_emb, rel_emb, agg_W, agg_b, usr_emb,
                                         mlp_W1, mlp_b1, mlp_W2, mlp_b2,
                                         mlp_W3, mlp_b3, mlp_W4, mlp_b4,
                                         se1, se2, se3, noise_e,
                                         fc1_W, fc1_b, fc2_W, fc2_b,
                                         u, v, t, click, adj_ent, adj_rel, out);
}